// round 16
// baseline (speedup 1.0000x reference)
#include <cuda_runtime.h>
#include <cuda_bf16.h>
#include <math.h>
#include <stdint.h>

// Model dims
#define BB 2
#define LL 2048
#define TT (BB*LL)      // 4096 tokens
#define DM 256
#define DI 512
#define NS 16
#define RR 16
#define KC 4
#define NL 4
#define DOUT 10

// scan chunking
#define NC 32
#define CL (LL/NC)      // 64
#define NU (BB*DI*NC)   // 32768

#define CT 8            // tokens per conv+xproj block

// ---------------- scratch (device globals; no allocation allowed) ----------------
__device__ float g_hidden[TT*DM];
__device__ float g_resid [TT*DM];
__device__ float g_norm  [TT*DM];
__device__ float g_xz    [TT*2*DI];
__device__ float g_xc    [TT*DI];
__device__ float g_xdbl  [TT*48];
__device__ float g_hend  [NU*NS];
__device__ float g_aprod [NU*NS];
__device__ float2 g_dxT  [(size_t)DI*TT];   // (delta, xc) transposed [d][t]
__device__ float  g_yT   [(size_t)DI*TT];   // scan output transposed [d][t]

// ---------------- f32x2 helpers ----------------
__device__ __forceinline__ void ffma2(uint64_t& d, uint64_t a, uint64_t b) {
    asm("fma.rn.f32x2 %0, %1, %2, %0;" : "+l"(d) : "l"(a), "l"(b));
}
__device__ __forceinline__ uint64_t dup2(float x) {
    uint64_t p;
    asm("mov.b64 %0, {%1, %1};" : "=l"(p) : "f"(x));
    return p;
}
__device__ __forceinline__ void unpack2(float& lo, float& hi, uint64_t v) {
    asm("mov.b64 {%0, %1}, %2;" : "=f"(lo), "=f"(hi) : "l"(v));
}
__device__ __forceinline__ float silu_f(float z) {
    return z / (1.f + __expf(-z));
}

// ---------------- profiling-alignment dummy ----------------
__global__ void dummy_kernel() {}

// ---------------- residual add + layernorm (first=1 gathers embedding) ----------
__global__ void addnorm_kernel(const float* __restrict__ hid, float* __restrict__ resid,
                               float* __restrict__ outp,
                               const float* __restrict__ w, const float* __restrict__ b,
                               const int* __restrict__ ids, const float* __restrict__ emb,
                               int first) {
    int t = blockIdx.x;
    int d = threadIdx.x;  // 256 threads
    size_t idx = (size_t)t*DM + d;
    float r;
    if (first) {
        r = emb[(size_t)ids[t]*DM + d];
    } else {
        r = hid[idx] + resid[idx];
    }
    resid[idx] = r;

    __shared__ float red1[8];
    __shared__ float red2[8];

    float s = r;
    #pragma unroll
    for (int o = 16; o > 0; o >>= 1) s += __shfl_xor_sync(0xffffffffu, s, o);
    if ((d & 31) == 0) red1[d >> 5] = s;
    __syncthreads();
    float tot = 0.f;
    #pragma unroll
    for (int i = 0; i < 8; i++) tot += red1[i];
    float m = tot * (1.f/(float)DM);

    float diff = r - m;
    float s2 = diff*diff;
    #pragma unroll
    for (int o = 16; o > 0; o >>= 1) s2 += __shfl_xor_sync(0xffffffffu, s2, o);
    if ((d & 31) == 0) red2[d >> 5] = s2;
    __syncthreads();
    float tot2 = 0.f;
    #pragma unroll
    for (int i = 0; i < 8; i++) tot2 += red2[i];
    float v = tot2 * (1.f/(float)DM);

    outp[idx] = diff * rsqrtf(v + 1e-5f) * w[d] + b[d];
}

// ---------------- f32x2 SGEMM 128x128 (known good) -----------------------------
__global__ void __launch_bounds__(256, 2) sgemm_f2(
        const float* __restrict__ A, const float* __restrict__ W,
        float* __restrict__ C, int M, int N, int K) {
    const int BK = 16;
    __shared__ float As[2][BK][128];
    __shared__ float Bs[2][BK][128];
    int bm = blockIdx.y * 128;
    int bn = blockIdx.x * 128;
    int tid = threadIdx.x;
    int tx = tid & 15;
    int ty = tid >> 4;

    int r0 = tid >> 2;
    int kq = (tid & 3) * 4;

    const float* Aptr = A + (size_t)bm * K;
    const float* Wptr = W + (size_t)bn * K;

    uint64_t acc[4][8];
    #pragma unroll
    for (int i = 0; i < 4; i++)
        #pragma unroll
        for (int j = 0; j < 8; j++) acc[i][j] = 0ull;

    float4 ra0 = *(const float4*)&Aptr[(size_t)r0*K + kq];
    float4 ra1 = *(const float4*)&Aptr[(size_t)(r0+64)*K + kq];
    float4 rb0 = *(const float4*)&Wptr[(size_t)r0*K + kq];
    float4 rb1 = *(const float4*)&Wptr[(size_t)(r0+64)*K + kq];
    As[0][kq+0][r0] = ra0.x; As[0][kq+1][r0] = ra0.y; As[0][kq+2][r0] = ra0.z; As[0][kq+3][r0] = ra0.w;
    As[0][kq+0][r0+64] = ra1.x; As[0][kq+1][r0+64] = ra1.y; As[0][kq+2][r0+64] = ra1.z; As[0][kq+3][r0+64] = ra1.w;
    Bs[0][kq+0][r0] = rb0.x; Bs[0][kq+1][r0] = rb0.y; Bs[0][kq+2][r0] = rb0.z; Bs[0][kq+3][r0] = rb0.w;
    Bs[0][kq+0][r0+64] = rb1.x; Bs[0][kq+1][r0+64] = rb1.y; Bs[0][kq+2][r0+64] = rb1.z; Bs[0][kq+3][r0+64] = rb1.w;
    __syncthreads();

    int nk = K / BK;
    int buf = 0;
    for (int k0 = 0; k0 < nk; k0++) {
        if (k0 + 1 < nk) {
            int kb = (k0+1)*BK + kq;
            ra0 = *(const float4*)&Aptr[(size_t)r0*K + kb];
            ra1 = *(const float4*)&Aptr[(size_t)(r0+64)*K + kb];
            rb0 = *(const float4*)&Wptr[(size_t)r0*K + kb];
            rb1 = *(const float4*)&Wptr[(size_t)(r0+64)*K + kb];
        }
        #pragma unroll
        for (int k = 0; k < BK; k++) {
            const uint64_t* ap = (const uint64_t*)&As[buf][k][ty*8];
            uint64_t a0 = ap[0], a1 = ap[1], a2 = ap[2], a3 = ap[3];
            float4 b0 = *(const float4*)&Bs[buf][k][tx*4];
            float4 b1 = *(const float4*)&Bs[buf][k][64 + tx*4];
            uint64_t bb[8];
            bb[0]=dup2(b0.x); bb[1]=dup2(b0.y); bb[2]=dup2(b0.z); bb[3]=dup2(b0.w);
            bb[4]=dup2(b1.x); bb[5]=dup2(b1.y); bb[6]=dup2(b1.z); bb[7]=dup2(b1.w);
            #pragma unroll
            for (int j = 0; j < 8; j++) {
                ffma2(acc[0][j], a0, bb[j]);
                ffma2(acc[1][j], a1, bb[j]);
                ffma2(acc[2][j], a2, bb[j]);
                ffma2(acc[3][j], a3, bb[j]);
            }
        }
        if (k0 + 1 < nk) {
            int nb = buf ^ 1;
            As[nb][kq+0][r0] = ra0.x; As[nb][kq+1][r0] = ra0.y; As[nb][kq+2][r0] = ra0.z; As[nb][kq+3][r0] = ra0.w;
            As[nb][kq+0][r0+64] = ra1.x; As[nb][kq+1][r0+64] = ra1.y; As[nb][kq+2][r0+64] = ra1.z; As[nb][kq+3][r0+64] = ra1.w;
            Bs[nb][kq+0][r0] = rb0.x; Bs[nb][kq+1][r0] = rb0.y; Bs[nb][kq+2][r0] = rb0.z; Bs[nb][kq+3][r0] = rb0.w;
            Bs[nb][kq+0][r0+64] = rb1.x; Bs[nb][kq+1][r0+64] = rb1.y; Bs[nb][kq+2][r0+64] = rb1.z; Bs[nb][kq+3][r0+64] = rb1.w;
        }
        __syncthreads();
        buf ^= 1;
    }

    #pragma unroll
    for (int i = 0; i < 4; i++) {
        float lo[8], hi[8];
        #pragma unroll
        for (int j = 0; j < 8; j++) unpack2(lo[j], hi[j], acc[i][j]);
        int m0 = bm + ty*8 + 2*i;
        *(float4*)&C[(size_t)m0*N + bn + tx*4]          = make_float4(lo[0],lo[1],lo[2],lo[3]);
        *(float4*)&C[(size_t)m0*N + bn + 64 + tx*4]     = make_float4(lo[4],lo[5],lo[6],lo[7]);
        *(float4*)&C[(size_t)(m0+1)*N + bn + tx*4]      = make_float4(hi[0],hi[1],hi[2],hi[3]);
        *(float4*)&C[(size_t)(m0+1)*N + bn + 64 + tx*4] = make_float4(hi[4],hi[5],hi[6],hi[7]);
    }
}

// ---------------- fused out_proj: A = ypost(yT, xc, xz) on the fly --------------
__global__ void __launch_bounds__(256) sgemm_f2_out(
        const float* __restrict__ yT, const float* __restrict__ xc,
        const float* __restrict__ xz, const float* __restrict__ Dp,
        const float* __restrict__ W, float* __restrict__ C, int M, int N, int K) {
    const int BK = 16;
    __shared__ float As[2][BK][64];
    __shared__ float Bs[2][BK][128];
    int bm = blockIdx.y * 64;
    int bn = blockIdx.x * 128;
    int tid = threadIdx.x;
    int tx = tid & 15;
    int ty = tid >> 4;

    int r0 = tid >> 2;            // token row within tile (0..63)
    int kq = (tid & 3) * 4;       // d offset 0,4,8,12

    int t = bm + r0;
    const float* Wptr = W + (size_t)bn * K;

    uint64_t acc[2][8];
    #pragma unroll
    for (int i = 0; i < 2; i++)
        #pragma unroll
        for (int j = 0; j < 8; j++) acc[i][j] = 0ull;

    auto loadA = [&](int kb) -> float4 {
        float4 xcv = *(const float4*)&xc[(size_t)t*DI + kb];
        float4 zv  = *(const float4*)&xz[(size_t)t*(2*DI) + DI + kb];
        float4 dpv = *(const float4*)&Dp[kb];
        float y0 = yT[(size_t)(kb+0)*TT + t];
        float y1 = yT[(size_t)(kb+1)*TT + t];
        float y2 = yT[(size_t)(kb+2)*TT + t];
        float y3 = yT[(size_t)(kb+3)*TT + t];
        float4 a;
        a.x = (y0 + dpv.x*xcv.x) * silu_f(zv.x);
        a.y = (y1 + dpv.y*xcv.y) * silu_f(zv.y);
        a.z = (y2 + dpv.z*xcv.z) * silu_f(zv.z);
        a.w = (y3 + dpv.w*xcv.w) * silu_f(zv.w);
        return a;
    };

    float4 ra0 = loadA(kq);
    float4 rb0 = *(const float4*)&Wptr[(size_t)r0*K + kq];
    float4 rb1 = *(const float4*)&Wptr[(size_t)(r0+64)*K + kq];
    As[0][kq+0][r0] = ra0.x; As[0][kq+1][r0] = ra0.y; As[0][kq+2][r0] = ra0.z; As[0][kq+3][r0] = ra0.w;
    Bs[0][kq+0][r0] = rb0.x; Bs[0][kq+1][r0] = rb0.y; Bs[0][kq+2][r0] = rb0.z; Bs[0][kq+3][r0] = rb0.w;
    Bs[0][kq+0][r0+64] = rb1.x; Bs[0][kq+1][r0+64] = rb1.y; Bs[0][kq+2][r0+64] = rb1.z; Bs[0][kq+3][r0+64] = rb1.w;
    __syncthreads();

    int nk = K / BK;
    int buf = 0;
    for (int k0 = 0; k0 < nk; k0++) {
        if (k0 + 1 < nk) {
            int kb = (k0+1)*BK + kq;
            ra0 = loadA(kb);
            rb0 = *(const float4*)&Wptr[(size_t)r0*K + kb];
            rb1 = *(const float4*)&Wptr[(size_t)(r0+64)*K + kb];
        }
        #pragma unroll
        for (int k = 0; k < BK; k++) {
            const uint64_t* ap = (const uint64_t*)&As[buf][k][ty*4];
            uint64_t a0 = ap[0], a1 = ap[1];
            float4 b0 = *(const float4*)&Bs[buf][k][tx*4];
            float4 b1 = *(const float4*)&Bs[buf][k][64 + tx*4];
            uint64_t bb[8];
            bb[0]=dup2(b0.x); bb[1]=dup2(b0.y); bb[2]=dup2(b0.z); bb[3]=dup2(b0.w);
            bb[4]=dup2(b1.x); bb[5]=dup2(b1.y); bb[6]=dup2(b1.z); bb[7]=dup2(b1.w);
            #pragma unroll
            for (int j = 0; j < 8; j++) {
                ffma2(acc[0][j], a0, bb[j]);
                ffma2(acc[1][j], a1, bb[j]);
            }
        }
        if (k0 + 1 < nk) {
            int nb = buf ^ 1;
            As[nb][kq+0][r0] = ra0.x; As[nb][kq+1][r0] = ra0.y; As[nb][kq+2][r0] = ra0.z; As[nb][kq+3][r0] = ra0.w;
            Bs[nb][kq+0][r0] = rb0.x; Bs[nb][kq+1][r0] = rb0.y; Bs[nb][kq+2][r0] = rb0.z; Bs[nb][kq+3][r0] = rb0.w;
            Bs[nb][kq+0][r0+64] = rb1.x; Bs[nb][kq+1][r0+64] = rb1.y; Bs[nb][kq+2][r0+64] = rb1.z; Bs[nb][kq+3][r0+64] = rb1.w;
        }
        __syncthreads();
        buf ^= 1;
    }

    #pragma unroll
    for (int i = 0; i < 2; i++) {
        float lo[8], hi[8];
        #pragma unroll
        for (int j = 0; j < 8; j++) unpack2(lo[j], hi[j], acc[i][j]);
        int m0 = bm + ty*4 + 2*i;
        *(float4*)&C[(size_t)m0*N + bn + tx*4]          = make_float4(lo[0],lo[1],lo[2],lo[3]);
        *(float4*)&C[(size_t)m0*N + bn + 64 + tx*4]     = make_float4(lo[4],lo[5],lo[6],lo[7]);
        *(float4*)&C[(size_t)(m0+1)*N + bn + tx*4]      = make_float4(hi[0],hi[1],hi[2],hi[3]);
        *(float4*)&C[(size_t)(m0+1)*N + bn + 64 + tx*4] = make_float4(hi[4],hi[5],hi[6],hi[7]);
    }
}

// ---------------- fused conv_silu + x_proj (CT=8, 512 blocks) -------------------
__global__ void __launch_bounds__(256) convxp_kernel(
        const float* __restrict__ xz, const float* __restrict__ cw,
        const float* __restrict__ cb, const float* __restrict__ W,
        float* __restrict__ xc, float* __restrict__ Cout) {
    __shared__ float As[DI][CT+1];   // 512 x 9
    __shared__ float Ws[48][68];     // 64-k chunk (+4 pad)
    int t0 = blockIdx.x * CT;
    int tid = threadIdx.x;

    // phase 1: conv + silu
    #pragma unroll
    for (int i = 0; i < (CT*DI)/256; i++) {    // 16
        int idx = tid + i*256;
        int d = idx & (DI-1);
        int m = idx >> 9;
        int t = t0 + m;
        int l = t & (LL-1);
        float acc = cb[d];
        #pragma unroll
        for (int j = 0; j < KC; j++) {
            int lo = l + j - (KC-1);
            if (lo >= 0)
                acc = fmaf(xz[(size_t)(t + j - (KC-1))*(2*DI) + d], cw[d*KC + j], acc);
        }
        float sv = silu_f(acc);
        As[d][m] = sv;
        xc[(size_t)t*DI + d] = sv;
    }
    __syncthreads();

    // phase 2: xdbl[CT,48] = As^T @ W^T
    int m = tid & 7;                 // token
    int g = tid >> 3;                // 0..31; handles n=g and (g<16) n=g+32
    float acc0 = 0.f, acc1 = 0.f;
    for (int kc = 0; kc < DI; kc += 64) {
        for (int i = tid; i < 48*16; i += 256) {
            int n = i >> 4, kq = (i & 15) * 4;
            float4 v = *(const float4*)&W[(size_t)n*DI + kc + kq];
            *(float4*)&Ws[n][kq] = v;
        }
        __syncthreads();
        #pragma unroll
        for (int k = 0; k < 64; k += 4) {
            float a0 = As[kc+k+0][m];
            float a1 = As[kc+k+1][m];
            float a2 = As[kc+k+2][m];
            float a3 = As[kc+k+3][m];
            float4 w0 = *(const float4*)&Ws[g][k];
            acc0 = fmaf(a3,w0.w, fmaf(a2,w0.z, fmaf(a1,w0.y, fmaf(a0,w0.x, acc0))));
            if (g < 16) {
                float4 w1 = *(const float4*)&Ws[g+32][k];
                acc1 = fmaf(a3,w1.w, fmaf(a2,w1.z, fmaf(a1,w1.y, fmaf(a0,w1.x, acc1))));
            }
        }
        __syncthreads();
    }
    size_t ob = (size_t)(t0 + m)*48;
    Cout[ob + g] = acc0;
    if (g < 16) Cout[ob + g + 32] = acc1;
}

// ---------------- prep: dt_proj + softplus + (delta,xc) transpose pack ----------
__global__ void __launch_bounds__(256) prep_kernel(
        const float* __restrict__ xdbl, const float* __restrict__ dtw,
        const float* __restrict__ dtb, const float* __restrict__ xc,
        float2* __restrict__ dxT) {
    __shared__ float s_dt[64][17];
    __shared__ float s_dw[64][17];
    __shared__ float s_db[64];
    __shared__ float s_del[64][65];
    __shared__ float s_xv [64][65];
    int t0 = blockIdx.x * 64;
    int d0 = blockIdx.y * 64;
    int tid = threadIdx.x;

    #pragma unroll
    for (int u = 0; u < 4; u++) {
        int id = tid + u*256;
        int t = id >> 4, r = id & 15;
        s_dt[t][r] = xdbl[(size_t)(t0+t)*48 + r];
        s_dw[t][r] = dtw[(size_t)(d0+t)*RR + r];
    }
    if (tid < 64) s_db[tid] = dtb[d0 + tid];
    __syncthreads();

    {
        int d = tid & 63;
        int tq = tid >> 6;
        #pragma unroll
        for (int j = 0; j < 16; j++) {
            int t = tq*16 + j;
            float acc = s_db[d];
            #pragma unroll
            for (int r = 0; r < RR; r++)
                acc = fmaf(s_dt[t][r], s_dw[d][r], acc);
            float sp = (acc > 20.f) ? acc : log1pf(__expf(acc));
            s_del[t][d] = sp;
            s_xv [t][d] = xc[(size_t)(t0+t)*DI + d0 + d];
        }
    }
    __syncthreads();

    {
        int t = tid & 63;
        int dq = tid >> 6;
        #pragma unroll
        for (int j = 0; j < 16; j++) {
            int d = dq*16 + j;
            dxT[(size_t)(d0+d)*TT + t0 + t] = make_float2(s_del[t][d], s_xv[t][d]);
        }
    }
}

// ---------------- chunked scan phase A: (b,c)-major units, B staged in smem ----
__global__ void __launch_bounds__(256) scan_partA(
        const float2* __restrict__ dxT, const float* __restrict__ xdbl,
        const float* __restrict__ A_log,
        float* __restrict__ hend, float* __restrict__ aprod) {
    __shared__ float s_b[CL][NS];
    int bc = blockIdx.x >> 5;
    int c  = bc & (NC-1);
    int b  = bc >> 5;
    int d0 = (blockIdx.x & 31) * 16;
    int tid = threadIdx.x;
    int lane = tid & 31;
    int n = lane & 15;
    int u = ((tid >> 5) << 1) + (lane >> 4);
    int d = d0 + u;
    size_t tg0 = (size_t)b*LL + (size_t)c*CL;

    for (int idx = tid; idx < CL*NS; idx += 256) {
        int t = idx >> 4, j = idx & 15;
        s_b[t][j] = xdbl[(tg0 + t)*48 + RR + j];
    }
    __syncthreads();

    float A = -__expf(A_log[d*NS + n]);
    float h = 0.f, ap = 1.f;
    const float2* dx = dxT + (size_t)d*TT + tg0;

    #pragma unroll 4
    for (int i = 0; i < CL; i++) {
        float2 v = dx[i];
        float bv = s_b[i][n];
        float dA = __expf(v.x * A);
        h = fmaf(dA, h, v.x * bv * v.y);
        ap *= dA;
    }
    int unit = (b*NC + c)*DI + d;
    hend [unit*NS + n] = h;
    aprod[unit*NS + n] = ap;
}

// ---------------- chunked scan phase C: staged B/C + inline prefix --------------
__global__ void __launch_bounds__(256) scan_partC(
        const float2* __restrict__ dxT, const float* __restrict__ xdbl,
        const float* __restrict__ A_log,
        const float* __restrict__ hend, const float* __restrict__ aprod,
        float* __restrict__ yT) {
    __shared__ float s_bc[CL][2*NS];
    int bc = blockIdx.x >> 5;
    int c  = bc & (NC-1);
    int b  = bc >> 5;
    int d0 = (blockIdx.x & 31) * 16;
    int tid = threadIdx.x;
    int lane = tid & 31;
    int n = lane & 15;
    int u = ((tid >> 5) << 1) + (lane >> 4);
    int d = d0 + u;
    size_t tg0 = (size_t)b*LL + (size_t)c*CL;

    for (int idx = tid; idx < CL*2*NS; idx += 256) {
        int t = idx >> 5, j = idx & 31;
        s_bc[t][j] = xdbl[(tg0 + t)*48 + RR + j];
    }
    __syncthreads();

    float A = -__expf(A_log[d*NS + n]);

    float h = 0.f;
    int base2 = (b*NC*DI + d)*NS + n;
    for (int cc = 0; cc < c; cc++) {
        int idx = base2 + cc*DI*NS;
        h = fmaf(aprod[idx], h, hend[idx]);
    }

    const float2* dx = dxT + (size_t)d*TT + tg0;
    float* yo = yT + (size_t)d*TT + tg0;

    #pragma unroll 4
    for (int i = 0; i < CL; i++) {
        float2 v = dx[i];
        float bv = s_bc[i][n];
        float cv = s_bc[i][NS + n];
        float dA = __expf(v.x * A);
        h = fmaf(dA, h, v.x * bv * v.y);
        float prod = h * cv;
        #pragma unroll
        for (int s = 1; s < 16; s <<= 1)
            prod += __shfl_xor_sync(0xffffffffu, prod, s);
        if (n == 0) yo[i] = prod;
    }
}

// ---------------- mean-pool over L + decode ----------------
__global__ void pool_decode_kernel(const float* __restrict__ normed,
                                   const float* __restrict__ dec_w,
                                   const float* __restrict__ dec_b,
                                   float* __restrict__ out) {
    int b = blockIdx.x;
    int tid = threadIdx.x;       // 1024
    int d = tid & 255;
    int c = tid >> 8;            // 0..3
    float s = 0.f;
    #pragma unroll 4
    for (int l = c*512; l < (c+1)*512; l++)
        s += normed[((size_t)b*LL + l)*DM + d];
    __shared__ float part[4][DM];
    __shared__ float pooled[DM];
    part[c][d] = s;
    __syncthreads();
    if (c == 0) {
        float tot = part[0][d] + part[1][d] + part[2][d] + part[3][d];
        pooled[d] = tot * (1.f/(float)LL);
    }
    __syncthreads();
    if (tid < DOUT) {
        float o = dec_b[tid];
        #pragma unroll 8
        for (int k = 0; k < DM; k++) o = fmaf(pooled[k], dec_w[tid*DM + k], o);
        out[b*DOUT + tid] = o;
    }
}

// ---------------- host ----------------
extern "C" void kernel_launch(void* const* d_in, const int* in_sizes, int n_in,
                              void* d_out, int out_size) {
    const int*   ids     = (const int*)d_in[0];
    const float* emb     = (const float*)d_in[1];
    const float* norm_w  = (const float*)d_in[2];
    const float* norm_b  = (const float*)d_in[3];
    const float* in_w    = (const float*)d_in[4];
    const float* conv_w  = (const float*)d_in[5];
    const float* conv_b  = (const float*)d_in[6];
    const float* xp_w    = (const float*)d_in[7];
    const float* dt_w    = (const float*)d_in[8];
    const float* dt_b    = (const float*)d_in[9];
    const float* A_log   = (const float*)d_in[10];
    const float* Dp      = (const float*)d_in[11];
    const float* out_w   = (const float*)d_in[12];
    const float* normf_w = (const float*)d_in[13];
    const float* normf_b = (const float*)d_in[14];
    const float* dec_w   = (const float*)d_in[15];
    const float* dec_b   = (const float*)d_in[16];
    float* out = (float*)d_out;

    float *p_hidden, *p_resid, *p_norm, *p_xz, *p_xc, *p_xdbl;
    float *p_hend, *p_aprod, *p_yT;
    float2 *p_dxT;
    cudaGetSymbolAddress((void**)&p_hidden, g_hidden);
    cudaGetSymbolAddress((void**)&p_resid,  g_resid);
    cudaGetSymbolAddress((void**)&p_norm,   g_norm);
    cudaGetSymbolAddress((void**)&p_xz,     g_xz);
    cudaGetSymbolAddress((void**)&p_xc,     g_xc);
    cudaGetSymbolAddress((void**)&p_xdbl,   g_xdbl);
    cudaGetSymbolAddress((void**)&p_hend,   g_hend);
    cudaGetSymbolAddress((void**)&p_aprod,  g_aprod);
    cudaGetSymbolAddress((void**)&p_dxT,    g_dxT);
    cudaGetSymbolAddress((void**)&p_yT,     g_yT);

    for (int i = 0; i < NL; i++) {
        addnorm_kernel<<<TT, DM>>>(p_hidden, p_resid, p_norm,
                                   norm_w + i*DM, norm_b + i*DM,
                                   ids, emb, i == 0);
        if (i == 0) dummy_kernel<<<1, 32>>>();   // profiled slot -> convxp fused kernel
        // in_proj: [TT,DM] x [2DI,DM]^T -> [TT,2DI]
        {
            dim3 g((2*DI)/128, TT/128);
            sgemm_f2<<<g, 256>>>(p_norm, in_w + (size_t)i*2*DI*DM, p_xz, TT, 2*DI, DM);
        }
        // fused conv+silu+x_proj: writes xc and xdbl
        convxp_kernel<<<TT/CT, 256>>>(p_xz, conv_w + i*DI*KC, conv_b + i*DI,
                                      xp_w + (size_t)i*48*DI, p_xc, p_xdbl);
        // prep: dt_proj + softplus + transpose pack (delta, xc) -> dxT
        {
            dim3 g(TT/64, DI/64);
            prep_kernel<<<g, 256>>>(p_xdbl, dt_w + (size_t)i*DI*RR, dt_b + i*DI,
                                    p_xc, p_dxT);
        }
        // chunked selective scan ((b,c)-major units, staged B/C, inline prefix)
        scan_partA<<<2048, 256>>>(p_dxT, p_xdbl, A_log + (size_t)i*DI*NS,
                                  p_hend, p_aprod);
        scan_partC<<<2048, 256>>>(p_dxT, p_xdbl, A_log + (size_t)i*DI*NS,
                                  p_hend, p_aprod, p_yT);
        // fused out_proj (ypost folded into A-tile load)
        {
            dim3 g(DM/128, TT/64);
            sgemm_f2_out<<<g, 256>>>(p_yT, p_xc, p_xz, Dp + i*DI,
                                     out_w + (size_t)i*DM*DI, p_hidden, TT, DM, DI);
        }
    }

    addnorm_kernel<<<TT, DM>>>(p_hidden, p_resid, p_norm, normf_w, normf_b,
                               ids, emb, 0);
    pool_decode_kernel<<<BB, 1024>>>(p_norm, dec_w, dec_b, out);
}

// round 17
// speedup vs baseline: 1.0196x; 1.0196x over previous
#include <cuda_runtime.h>
#include <cuda_bf16.h>
#include <math.h>
#include <stdint.h>

// Model dims
#define BB 2
#define LL 2048
#define TT (BB*LL)      // 4096 tokens
#define DM 256
#define DI 512
#define NS 16
#define RR 16
#define KC 4
#define NL 4
#define DOUT 10

// scan chunking
#define NC 32
#define CL (LL/NC)      // 64
#define NU (BB*DI*NC)   // 32768

#define CT 16           // tokens per conv+xproj block

// ---------------- scratch (device globals; no allocation allowed) ----------------
__device__ float g_hidden[TT*DM];
__device__ float g_resid [TT*DM];
__device__ float g_norm  [TT*DM];
__device__ float g_xz    [TT*2*DI];
__device__ float g_xc    [TT*DI];
__device__ float g_xdbl  [TT*48];
__device__ float g_hend  [NU*NS];
__device__ float g_aprod [NU*NS];
__device__ float2 g_dxT  [(size_t)DI*TT];   // (delta, xc) transposed [d][t]
__device__ float  g_yT   [(size_t)DI*TT];   // scan output transposed [d][t]

// ---------------- f32x2 helpers ----------------
__device__ __forceinline__ void ffma2(uint64_t& d, uint64_t a, uint64_t b) {
    asm("fma.rn.f32x2 %0, %1, %2, %0;" : "+l"(d) : "l"(a), "l"(b));
}
__device__ __forceinline__ uint64_t dup2(float x) {
    uint64_t p;
    asm("mov.b64 %0, {%1, %1};" : "=l"(p) : "f"(x));
    return p;
}
__device__ __forceinline__ void unpack2(float& lo, float& hi, uint64_t v) {
    asm("mov.b64 {%0, %1}, %2;" : "=f"(lo), "=f"(hi) : "l"(v));
}
__device__ __forceinline__ float silu_f(float z) {
    return z / (1.f + __expf(-z));
}

// ---------------- profiling-alignment dummy ----------------
__global__ void dummy_kernel() {}

// ---------------- residual add + layernorm (first=1 gathers embedding) ----------
__global__ void addnorm_kernel(const float* __restrict__ hid, float* __restrict__ resid,
                               float* __restrict__ outp,
                               const float* __restrict__ w, const float* __restrict__ b,
                               const int* __restrict__ ids, const float* __restrict__ emb,
                               int first) {
    int t = blockIdx.x;
    int d = threadIdx.x;  // 256 threads
    size_t idx = (size_t)t*DM + d;
    float r;
    if (first) {
        r = emb[(size_t)ids[t]*DM + d];
    } else {
        r = hid[idx] + resid[idx];
    }
    resid[idx] = r;

    __shared__ float red1[8];
    __shared__ float red2[8];

    float s = r;
    #pragma unroll
    for (int o = 16; o > 0; o >>= 1) s += __shfl_xor_sync(0xffffffffu, s, o);
    if ((d & 31) == 0) red1[d >> 5] = s;
    __syncthreads();
    float tot = 0.f;
    #pragma unroll
    for (int i = 0; i < 8; i++) tot += red1[i];
    float m = tot * (1.f/(float)DM);

    float diff = r - m;
    float s2 = diff*diff;
    #pragma unroll
    for (int o = 16; o > 0; o >>= 1) s2 += __shfl_xor_sync(0xffffffffu, s2, o);
    if ((d & 31) == 0) red2[d >> 5] = s2;
    __syncthreads();
    float tot2 = 0.f;
    #pragma unroll
    for (int i = 0; i < 8; i++) tot2 += red2[i];
    float v = tot2 * (1.f/(float)DM);

    outp[idx] = diff * rsqrtf(v + 1e-5f) * w[d] + b[d];
}

// ---------------- f32x2 SGEMM 128x128 (known good) -----------------------------
__global__ void __launch_bounds__(256, 2) sgemm_f2(
        const float* __restrict__ A, const float* __restrict__ W,
        float* __restrict__ C, int M, int N, int K) {
    const int BK = 16;
    __shared__ float As[2][BK][128];
    __shared__ float Bs[2][BK][128];
    int bm = blockIdx.y * 128;
    int bn = blockIdx.x * 128;
    int tid = threadIdx.x;
    int tx = tid & 15;
    int ty = tid >> 4;

    int r0 = tid >> 2;
    int kq = (tid & 3) * 4;

    const float* Aptr = A + (size_t)bm * K;
    const float* Wptr = W + (size_t)bn * K;

    uint64_t acc[4][8];
    #pragma unroll
    for (int i = 0; i < 4; i++)
        #pragma unroll
        for (int j = 0; j < 8; j++) acc[i][j] = 0ull;

    float4 ra0 = *(const float4*)&Aptr[(size_t)r0*K + kq];
    float4 ra1 = *(const float4*)&Aptr[(size_t)(r0+64)*K + kq];
    float4 rb0 = *(const float4*)&Wptr[(size_t)r0*K + kq];
    float4 rb1 = *(const float4*)&Wptr[(size_t)(r0+64)*K + kq];
    As[0][kq+0][r0] = ra0.x; As[0][kq+1][r0] = ra0.y; As[0][kq+2][r0] = ra0.z; As[0][kq+3][r0] = ra0.w;
    As[0][kq+0][r0+64] = ra1.x; As[0][kq+1][r0+64] = ra1.y; As[0][kq+2][r0+64] = ra1.z; As[0][kq+3][r0+64] = ra1.w;
    Bs[0][kq+0][r0] = rb0.x; Bs[0][kq+1][r0] = rb0.y; Bs[0][kq+2][r0] = rb0.z; Bs[0][kq+3][r0] = rb0.w;
    Bs[0][kq+0][r0+64] = rb1.x; Bs[0][kq+1][r0+64] = rb1.y; Bs[0][kq+2][r0+64] = rb1.z; Bs[0][kq+3][r0+64] = rb1.w;
    __syncthreads();

    int nk = K / BK;
    int buf = 0;
    for (int k0 = 0; k0 < nk; k0++) {
        if (k0 + 1 < nk) {
            int kb = (k0+1)*BK + kq;
            ra0 = *(const float4*)&Aptr[(size_t)r0*K + kb];
            ra1 = *(const float4*)&Aptr[(size_t)(r0+64)*K + kb];
            rb0 = *(const float4*)&Wptr[(size_t)r0*K + kb];
            rb1 = *(const float4*)&Wptr[(size_t)(r0+64)*K + kb];
        }
        #pragma unroll
        for (int k = 0; k < BK; k++) {
            const uint64_t* ap = (const uint64_t*)&As[buf][k][ty*8];
            uint64_t a0 = ap[0], a1 = ap[1], a2 = ap[2], a3 = ap[3];
            float4 b0 = *(const float4*)&Bs[buf][k][tx*4];
            float4 b1 = *(const float4*)&Bs[buf][k][64 + tx*4];
            uint64_t bb[8];
            bb[0]=dup2(b0.x); bb[1]=dup2(b0.y); bb[2]=dup2(b0.z); bb[3]=dup2(b0.w);
            bb[4]=dup2(b1.x); bb[5]=dup2(b1.y); bb[6]=dup2(b1.z); bb[7]=dup2(b1.w);
            #pragma unroll
            for (int j = 0; j < 8; j++) {
                ffma2(acc[0][j], a0, bb[j]);
                ffma2(acc[1][j], a1, bb[j]);
                ffma2(acc[2][j], a2, bb[j]);
                ffma2(acc[3][j], a3, bb[j]);
            }
        }
        if (k0 + 1 < nk) {
            int nb = buf ^ 1;
            As[nb][kq+0][r0] = ra0.x; As[nb][kq+1][r0] = ra0.y; As[nb][kq+2][r0] = ra0.z; As[nb][kq+3][r0] = ra0.w;
            As[nb][kq+0][r0+64] = ra1.x; As[nb][kq+1][r0+64] = ra1.y; As[nb][kq+2][r0+64] = ra1.z; As[nb][kq+3][r0+64] = ra1.w;
            Bs[nb][kq+0][r0] = rb0.x; Bs[nb][kq+1][r0] = rb0.y; Bs[nb][kq+2][r0] = rb0.z; Bs[nb][kq+3][r0] = rb0.w;
            Bs[nb][kq+0][r0+64] = rb1.x; Bs[nb][kq+1][r0+64] = rb1.y; Bs[nb][kq+2][r0+64] = rb1.z; Bs[nb][kq+3][r0+64] = rb1.w;
        }
        __syncthreads();
        buf ^= 1;
    }

    #pragma unroll
    for (int i = 0; i < 4; i++) {
        float lo[8], hi[8];
        #pragma unroll
        for (int j = 0; j < 8; j++) unpack2(lo[j], hi[j], acc[i][j]);
        int m0 = bm + ty*8 + 2*i;
        *(float4*)&C[(size_t)m0*N + bn + tx*4]          = make_float4(lo[0],lo[1],lo[2],lo[3]);
        *(float4*)&C[(size_t)m0*N + bn + 64 + tx*4]     = make_float4(lo[4],lo[5],lo[6],lo[7]);
        *(float4*)&C[(size_t)(m0+1)*N + bn + tx*4]      = make_float4(hi[0],hi[1],hi[2],hi[3]);
        *(float4*)&C[(size_t)(m0+1)*N + bn + 64 + tx*4] = make_float4(hi[4],hi[5],hi[6],hi[7]);
    }
}

// ---------------- fused out_proj: A = ypost(yT, xc, xz) on the fly --------------
__global__ void __launch_bounds__(256) sgemm_f2_out(
        const float* __restrict__ yT, const float* __restrict__ xc,
        const float* __restrict__ xz, const float* __restrict__ Dp,
        const float* __restrict__ W, float* __restrict__ C, int M, int N, int K) {
    const int BK = 16;
    __shared__ float As[2][BK][64];
    __shared__ float Bs[2][BK][128];
    int bm = blockIdx.y * 64;
    int bn = blockIdx.x * 128;
    int tid = threadIdx.x;
    int tx = tid & 15;
    int ty = tid >> 4;

    int r0 = tid >> 2;            // token row within tile (0..63)
    int kq = (tid & 3) * 4;       // d offset 0,4,8,12

    int t = bm + r0;
    const float* Wptr = W + (size_t)bn * K;

    uint64_t acc[2][8];
    #pragma unroll
    for (int i = 0; i < 2; i++)
        #pragma unroll
        for (int j = 0; j < 8; j++) acc[i][j] = 0ull;

    auto loadA = [&](int kb) -> float4 {
        float4 xcv = *(const float4*)&xc[(size_t)t*DI + kb];
        float4 zv  = *(const float4*)&xz[(size_t)t*(2*DI) + DI + kb];
        float4 dpv = *(const float4*)&Dp[kb];
        float y0 = yT[(size_t)(kb+0)*TT + t];
        float y1 = yT[(size_t)(kb+1)*TT + t];
        float y2 = yT[(size_t)(kb+2)*TT + t];
        float y3 = yT[(size_t)(kb+3)*TT + t];
        float4 a;
        a.x = (y0 + dpv.x*xcv.x) * silu_f(zv.x);
        a.y = (y1 + dpv.y*xcv.y) * silu_f(zv.y);
        a.z = (y2 + dpv.z*xcv.z) * silu_f(zv.z);
        a.w = (y3 + dpv.w*xcv.w) * silu_f(zv.w);
        return a;
    };

    float4 ra0 = loadA(kq);
    float4 rb0 = *(const float4*)&Wptr[(size_t)r0*K + kq];
    float4 rb1 = *(const float4*)&Wptr[(size_t)(r0+64)*K + kq];
    As[0][kq+0][r0] = ra0.x; As[0][kq+1][r0] = ra0.y; As[0][kq+2][r0] = ra0.z; As[0][kq+3][r0] = ra0.w;
    Bs[0][kq+0][r0] = rb0.x; Bs[0][kq+1][r0] = rb0.y; Bs[0][kq+2][r0] = rb0.z; Bs[0][kq+3][r0] = rb0.w;
    Bs[0][kq+0][r0+64] = rb1.x; Bs[0][kq+1][r0+64] = rb1.y; Bs[0][kq+2][r0+64] = rb1.z; Bs[0][kq+3][r0+64] = rb1.w;
    __syncthreads();

    int nk = K / BK;
    int buf = 0;
    for (int k0 = 0; k0 < nk; k0++) {
        if (k0 + 1 < nk) {
            int kb = (k0+1)*BK + kq;
            ra0 = loadA(kb);
            rb0 = *(const float4*)&Wptr[(size_t)r0*K + kb];
            rb1 = *(const float4*)&Wptr[(size_t)(r0+64)*K + kb];
        }
        #pragma unroll
        for (int k = 0; k < BK; k++) {
            const uint64_t* ap = (const uint64_t*)&As[buf][k][ty*4];
            uint64_t a0 = ap[0], a1 = ap[1];
            float4 b0 = *(const float4*)&Bs[buf][k][tx*4];
            float4 b1 = *(const float4*)&Bs[buf][k][64 + tx*4];
            uint64_t bb[8];
            bb[0]=dup2(b0.x); bb[1]=dup2(b0.y); bb[2]=dup2(b0.z); bb[3]=dup2(b0.w);
            bb[4]=dup2(b1.x); bb[5]=dup2(b1.y); bb[6]=dup2(b1.z); bb[7]=dup2(b1.w);
            #pragma unroll
            for (int j = 0; j < 8; j++) {
                ffma2(acc[0][j], a0, bb[j]);
                ffma2(acc[1][j], a1, bb[j]);
            }
        }
        if (k0 + 1 < nk) {
            int nb = buf ^ 1;
            As[nb][kq+0][r0] = ra0.x; As[nb][kq+1][r0] = ra0.y; As[nb][kq+2][r0] = ra0.z; As[nb][kq+3][r0] = ra0.w;
            Bs[nb][kq+0][r0] = rb0.x; Bs[nb][kq+1][r0] = rb0.y; Bs[nb][kq+2][r0] = rb0.z; Bs[nb][kq+3][r0] = rb0.w;
            Bs[nb][kq+0][r0+64] = rb1.x; Bs[nb][kq+1][r0+64] = rb1.y; Bs[nb][kq+2][r0+64] = rb1.z; Bs[nb][kq+3][r0+64] = rb1.w;
        }
        __syncthreads();
        buf ^= 1;
    }

    #pragma unroll
    for (int i = 0; i < 2; i++) {
        float lo[8], hi[8];
        #pragma unroll
        for (int j = 0; j < 8; j++) unpack2(lo[j], hi[j], acc[i][j]);
        int m0 = bm + ty*4 + 2*i;
        *(float4*)&C[(size_t)m0*N + bn + tx*4]          = make_float4(lo[0],lo[1],lo[2],lo[3]);
        *(float4*)&C[(size_t)m0*N + bn + 64 + tx*4]     = make_float4(lo[4],lo[5],lo[6],lo[7]);
        *(float4*)&C[(size_t)(m0+1)*N + bn + tx*4]      = make_float4(hi[0],hi[1],hi[2],hi[3]);
        *(float4*)&C[(size_t)(m0+1)*N + bn + 64 + tx*4] = make_float4(hi[4],hi[5],hi[6],hi[7]);
    }
}

// ---------------- fused conv_silu + x_proj (CT=16, 512 threads) -----------------
__global__ void __launch_bounds__(512) convxp_kernel(
        const float* __restrict__ xz, const float* __restrict__ cw,
        const float* __restrict__ cb, const float* __restrict__ W,
        float* __restrict__ xc, float* __restrict__ Cout) {
    __shared__ float As[DI][CT+1];   // 512 x 17
    __shared__ float Ws[48][68];     // 64-k chunk (+4 pad)
    int t0 = blockIdx.x * CT;
    int tid = threadIdx.x;

    // phase 1: conv + silu
    #pragma unroll
    for (int i = 0; i < (CT*DI)/512; i++) {    // 16
        int idx = tid + i*512;
        int d = idx & (DI-1);
        int m = idx >> 9;
        int t = t0 + m;
        int l = t & (LL-1);
        float acc = cb[d];
        #pragma unroll
        for (int j = 0; j < KC; j++) {
            int lo = l + j - (KC-1);
            if (lo >= 0)
                acc = fmaf(xz[(size_t)(t + j - (KC-1))*(2*DI) + d], cw[d*KC + j], acc);
        }
        float sv = silu_f(acc);
        As[d][m] = sv;
        xc[(size_t)t*DI + d] = sv;
    }
    __syncthreads();

    // phase 2: xdbl[CT,48] = As^T @ W^T
    int m = tid & 15;                // token 0..15
    int g = tid >> 4;                // 0..31; handles n=g and (g<16) n=g+32
    float acc0 = 0.f, acc1 = 0.f;
    for (int kc = 0; kc < DI; kc += 64) {
        for (int i = tid; i < 48*16; i += 512) {
            int n = i >> 4, kq = (i & 15) * 4;
            float4 v = *(const float4*)&W[(size_t)n*DI + kc + kq];
            *(float4*)&Ws[n][kq] = v;
        }
        __syncthreads();
        #pragma unroll
        for (int k = 0; k < 64; k += 4) {
            float a0 = As[kc+k+0][m];
            float a1 = As[kc+k+1][m];
            float a2 = As[kc+k+2][m];
            float a3 = As[kc+k+3][m];
            float4 w0 = *(const float4*)&Ws[g][k];
            acc0 = fmaf(a3,w0.w, fmaf(a2,w0.z, fmaf(a1,w0.y, fmaf(a0,w0.x, acc0))));
            if (g < 16) {
                float4 w1 = *(const float4*)&Ws[g+32][k];
                acc1 = fmaf(a3,w1.w, fmaf(a2,w1.z, fmaf(a1,w1.y, fmaf(a0,w1.x, acc1))));
            }
        }
        __syncthreads();
    }
    size_t ob = (size_t)(t0 + m)*48;
    Cout[ob + g] = acc0;
    if (g < 16) Cout[ob + g + 32] = acc1;
}

// ---------------- prep: dt_proj + softplus + (delta,xc) transpose pack ----------
__global__ void __launch_bounds__(256) prep_kernel(
        const float* __restrict__ xdbl, const float* __restrict__ dtw,
        const float* __restrict__ dtb, const float* __restrict__ xc,
        float2* __restrict__ dxT) {
    __shared__ float s_dt[64][17];
    __shared__ float s_dw[64][17];
    __shared__ float s_db[64];
    __shared__ float s_del[64][65];
    __shared__ float s_xv [64][65];
    int t0 = blockIdx.x * 64;
    int d0 = blockIdx.y * 64;
    int tid = threadIdx.x;

    #pragma unroll
    for (int u = 0; u < 4; u++) {
        int id = tid + u*256;
        int t = id >> 4, r = id & 15;
        s_dt[t][r] = xdbl[(size_t)(t0+t)*48 + r];
        s_dw[t][r] = dtw[(size_t)(d0+t)*RR + r];
    }
    if (tid < 64) s_db[tid] = dtb[d0 + tid];
    __syncthreads();

    {
        int d = tid & 63;
        int tq = tid >> 6;
        #pragma unroll
        for (int j = 0; j < 16; j++) {
            int t = tq*16 + j;
            float acc = s_db[d];
            #pragma unroll
            for (int r = 0; r < RR; r++)
                acc = fmaf(s_dt[t][r], s_dw[d][r], acc);
            float sp = (acc > 20.f) ? acc : log1pf(__expf(acc));
            s_del[t][d] = sp;
            s_xv [t][d] = xc[(size_t)(t0+t)*DI + d0 + d];
        }
    }
    __syncthreads();

    {
        int t = tid & 63;
        int dq = tid >> 6;
        #pragma unroll
        for (int j = 0; j < 16; j++) {
            int d = dq*16 + j;
            dxT[(size_t)(d0+d)*TT + t0 + t] = make_float2(s_del[t][d], s_xv[t][d]);
        }
    }
}

// ---------------- chunked scan phase A: (b,c)-major units, B staged in smem ----
__global__ void __launch_bounds__(256) scan_partA(
        const float2* __restrict__ dxT, const float* __restrict__ xdbl,
        const float* __restrict__ A_log,
        float* __restrict__ hend, float* __restrict__ aprod) {
    __shared__ float s_b[CL][NS];
    int bc = blockIdx.x >> 5;
    int c  = bc & (NC-1);
    int b  = bc >> 5;
    int d0 = (blockIdx.x & 31) * 16;
    int tid = threadIdx.x;
    int lane = tid & 31;
    int n = lane & 15;
    int u = ((tid >> 5) << 1) + (lane >> 4);
    int d = d0 + u;
    size_t tg0 = (size_t)b*LL + (size_t)c*CL;

    for (int idx = tid; idx < CL*NS; idx += 256) {
        int t = idx >> 4, j = idx & 15;
        s_b[t][j] = xdbl[(tg0 + t)*48 + RR + j];
    }
    __syncthreads();

    float A = -__expf(A_log[d*NS + n]);
    float h = 0.f, ap = 1.f;
    const float2* dx = dxT + (size_t)d*TT + tg0;

    #pragma unroll 4
    for (int i = 0; i < CL; i++) {
        float2 v = dx[i];
        float bv = s_b[i][n];
        float dA = __expf(v.x * A);
        h = fmaf(dA, h, v.x * bv * v.y);
        ap *= dA;
    }
    int unit = (b*NC + c)*DI + d;
    hend [unit*NS + n] = h;
    aprod[unit*NS + n] = ap;
}

// ---------------- chunked scan phase C: staged B/C + inline prefix --------------
__global__ void __launch_bounds__(256) scan_partC(
        const float2* __restrict__ dxT, const float* __restrict__ xdbl,
        const float* __restrict__ A_log,
        const float* __restrict__ hend, const float* __restrict__ aprod,
        float* __restrict__ yT) {
    __shared__ float s_bc[CL][2*NS];
    int bc = blockIdx.x >> 5;
    int c  = bc & (NC-1);
    int b  = bc >> 5;
    int d0 = (blockIdx.x & 31) * 16;
    int tid = threadIdx.x;
    int lane = tid & 31;
    int n = lane & 15;
    int u = ((tid >> 5) << 1) + (lane >> 4);
    int d = d0 + u;
    size_t tg0 = (size_t)b*LL + (size_t)c*CL;

    for (int idx = tid; idx < CL*2*NS; idx += 256) {
        int t = idx >> 5, j = idx & 31;
        s_bc[t][j] = xdbl[(tg0 + t)*48 + RR + j];
    }
    __syncthreads();

    float A = -__expf(A_log[d*NS + n]);

    float h = 0.f;
    int base2 = (b*NC*DI + d)*NS + n;
    for (int cc = 0; cc < c; cc++) {
        int idx = base2 + cc*DI*NS;
        h = fmaf(aprod[idx], h, hend[idx]);
    }

    const float2* dx = dxT + (size_t)d*TT + tg0;
    float* yo = yT + (size_t)d*TT + tg0;

    #pragma unroll 4
    for (int i = 0; i < CL; i++) {
        float2 v = dx[i];
        float bv = s_bc[i][n];
        float cv = s_bc[i][NS + n];
        float dA = __expf(v.x * A);
        h = fmaf(dA, h, v.x * bv * v.y);
        float prod = h * cv;
        #pragma unroll
        for (int s = 1; s < 16; s <<= 1)
            prod += __shfl_xor_sync(0xffffffffu, prod, s);
        if (n == 0) yo[i] = prod;
    }
}

// ---------------- mean-pool over L + decode ----------------
__global__ void pool_decode_kernel(const float* __restrict__ normed,
                                   const float* __restrict__ dec_w,
                                   const float* __restrict__ dec_b,
                                   float* __restrict__ out) {
    int b = blockIdx.x;
    int tid = threadIdx.x;       // 1024
    int d = tid & 255;
    int c = tid >> 8;            // 0..3
    float s = 0.f;
    #pragma unroll 4
    for (int l = c*512; l < (c+1)*512; l++)
        s += normed[((size_t)b*LL + l)*DM + d];
    __shared__ float part[4][DM];
    __shared__ float pooled[DM];
    part[c][d] = s;
    __syncthreads();
    if (c == 0) {
        float tot = part[0][d] + part[1][d] + part[2][d] + part[3][d];
        pooled[d] = tot * (1.f/(float)LL);
    }
    __syncthreads();
    if (tid < DOUT) {
        float o = dec_b[tid];
        #pragma unroll 8
        for (int k = 0; k < DM; k++) o = fmaf(pooled[k], dec_w[tid*DM + k], o);
        out[b*DOUT + tid] = o;
    }
}

// ---------------- host ----------------
extern "C" void kernel_launch(void* const* d_in, const int* in_sizes, int n_in,
                              void* d_out, int out_size) {
    const int*   ids     = (const int*)d_in[0];
    const float* emb     = (const float*)d_in[1];
    const float* norm_w  = (const float*)d_in[2];
    const float* norm_b  = (const float*)d_in[3];
    const float* in_w    = (const float*)d_in[4];
    const float* conv_w  = (const float*)d_in[5];
    const float* conv_b  = (const float*)d_in[6];
    const float* xp_w    = (const float*)d_in[7];
    const float* dt_w    = (const float*)d_in[8];
    const float* dt_b    = (const float*)d_in[9];
    const float* A_log   = (const float*)d_in[10];
    const float* Dp      = (const float*)d_in[11];
    const float* out_w   = (const float*)d_in[12];
    const float* normf_w = (const float*)d_in[13];
    const float* normf_b = (const float*)d_in[14];
    const float* dec_w   = (const float*)d_in[15];
    const float* dec_b   = (const float*)d_in[16];
    float* out = (float*)d_out;

    float *p_hidden, *p_resid, *p_norm, *p_xz, *p_xc, *p_xdbl;
    float *p_hend, *p_aprod, *p_yT;
    float2 *p_dxT;
    cudaGetSymbolAddress((void**)&p_hidden, g_hidden);
    cudaGetSymbolAddress((void**)&p_resid,  g_resid);
    cudaGetSymbolAddress((void**)&p_norm,   g_norm);
    cudaGetSymbolAddress((void**)&p_xz,     g_xz);
    cudaGetSymbolAddress((void**)&p_xc,     g_xc);
    cudaGetSymbolAddress((void**)&p_xdbl,   g_xdbl);
    cudaGetSymbolAddress((void**)&p_hend,   g_hend);
    cudaGetSymbolAddress((void**)&p_aprod,  g_aprod);
    cudaGetSymbolAddress((void**)&p_dxT,    g_dxT);
    cudaGetSymbolAddress((void**)&p_yT,     g_yT);

    for (int i = 0; i < NL; i++) {
        addnorm_kernel<<<TT, DM>>>(p_hidden, p_resid, p_norm,
                                   norm_w + i*DM, norm_b + i*DM,
                                   ids, emb, i == 0);
        if (i == 0) dummy_kernel<<<1, 32>>>();   // profiled slot -> convxp fused kernel
        // in_proj: [TT,DM] x [2DI,DM]^T -> [TT,2DI]
        {
            dim3 g((2*DI)/128, TT/128);
            sgemm_f2<<<g, 256>>>(p_norm, in_w + (size_t)i*2*DI*DM, p_xz, TT, 2*DI, DM);
        }
        // fused conv+silu+x_proj: writes xc and xdbl
        convxp_kernel<<<TT/CT, 512>>>(p_xz, conv_w + i*DI*KC, conv_b + i*DI,
                                      xp_w + (size_t)i*48*DI, p_xc, p_xdbl);
        // prep: dt_proj + softplus + transpose pack (delta, xc) -> dxT
        {
            dim3 g(TT/64, DI/64);
            prep_kernel<<<g, 256>>>(p_xdbl, dt_w + (size_t)i*DI*RR, dt_b + i*DI,
                                    p_xc, p_dxT);
        }
        // chunked selective scan ((b,c)-major units, staged B/C, inline prefix)
        scan_partA<<<2048, 256>>>(p_dxT, p_xdbl, A_log + (size_t)i*DI*NS,
                                  p_hend, p_aprod);
        scan_partC<<<2048, 256>>>(p_dxT, p_xdbl, A_log + (size_t)i*DI*NS,
                                  p_hend, p_aprod, p_yT);
        // fused out_proj (ypost folded into A-tile load)
        {
            dim3 g(DM/128, TT/64);
            sgemm_f2_out<<<g, 256>>>(p_yT, p_xc, p_xz, Dp + i*DI,
                                     out_w + (size_t)i*DM*DI, p_hidden, TT, DM, DI);
        }
    }

    addnorm_kernel<<<TT, DM>>>(p_hidden, p_resid, p_norm, normf_w, normf_b,
                               ids, emb, 0);
    pool_decode_kernel<<<BB, 1024>>>(p_norm, dec_w, dec_b, out);
}